// round 5
// baseline (speedup 1.0000x reference)
#include <cuda_runtime.h>

#define N_NODES 100000
#define IN_DIM  256
#define OUT_DIM 128
#define N_EDGES 3200000

// Scratch for h = X @ W  (100000 x 128 fp32 = 51.2 MB). Static __device__ per
// allocation-guard rules.
__device__ float g_h[(size_t)N_NODES * OUT_DIM];

// ---------------------------------------------------------------------------
// Kernel 1: SGEMM  h = X[100000,256] @ W[256,128]
// 128x128 block tile, BK=16, 256 threads, 8x8 register tile per thread.
// ---------------------------------------------------------------------------
#define BM 128
#define BN 128
#define BK 16

__global__ __launch_bounds__(256) void gemm_kernel(
    const float* __restrict__ A,   // [N_NODES, IN_DIM]
    const float* __restrict__ W)   // [IN_DIM, OUT_DIM]
{
    __shared__ float As[BK][BM + 4];  // transposed A tile (+pad: conflict dodge)
    __shared__ float Bs[BK][BN];

    const int tid       = threadIdx.x;
    const int block_row = blockIdx.x * BM;
    const int ty        = tid >> 4;   // 0..15  (row group)
    const int tx        = tid & 15;   // 0..15  (col group)

    float acc[8][8];
#pragma unroll
    for (int i = 0; i < 8; i++)
#pragma unroll
        for (int j = 0; j < 8; j++) acc[i][j] = 0.0f;

#pragma unroll 1
    for (int kt = 0; kt < IN_DIM / BK; kt++) {
        const int k0 = kt * BK;

        // --- load A tile: 128 rows x 16 cols = 512 float4, 2 per thread ---
#pragma unroll
        for (int half = 0; half < 2; half++) {
            int idx = tid + half * 256;
            int row = idx >> 2;       // 0..127
            int c4  = idx & 3;        // 0..3 -> k offsets c4*4..c4*4+3
            int gr  = block_row + row;
            float4 v = make_float4(0.f, 0.f, 0.f, 0.f);
            if (gr < N_NODES)
                v = *(const float4*)&A[(size_t)gr * IN_DIM + k0 + c4 * 4];
            As[c4 * 4 + 0][row] = v.x;
            As[c4 * 4 + 1][row] = v.y;
            As[c4 * 4 + 2][row] = v.z;
            As[c4 * 4 + 3][row] = v.w;
        }

        // --- load B tile: 16 rows x 128 cols = 512 float4, 2 per thread ---
#pragma unroll
        for (int half = 0; half < 2; half++) {
            int idx = tid + half * 256;
            int row = idx >> 5;       // 0..15
            int c   = idx & 31;       // 0..31 -> float4 col group
            *(float4*)&Bs[row][c * 4] =
                *(const float4*)&W[(size_t)(k0 + row) * OUT_DIM + c * 4];
        }

        __syncthreads();

#pragma unroll
        for (int k = 0; k < BK; k++) {
            float a[8], bfr[8];
            *(float4*)&a[0]   = *(const float4*)&As[k][ty * 8];
            *(float4*)&a[4]   = *(const float4*)&As[k][ty * 8 + 4];
            *(float4*)&bfr[0] = *(const float4*)&Bs[k][tx * 8];
            *(float4*)&bfr[4] = *(const float4*)&Bs[k][tx * 8 + 4];
#pragma unroll
            for (int i = 0; i < 8; i++)
#pragma unroll
                for (int j = 0; j < 8; j++)
                    acc[i][j] = fmaf(a[i], bfr[j], acc[i][j]);
        }

        __syncthreads();
    }

    // --- epilogue: write h tile ---
#pragma unroll
    for (int i = 0; i < 8; i++) {
        int gr = block_row + ty * 8 + i;
        if (gr < N_NODES) {
            float* dst = &g_h[(size_t)gr * OUT_DIM + tx * 8];
            *(float4*)&dst[0] = make_float4(acc[i][0], acc[i][1], acc[i][2], acc[i][3]);
            *(float4*)&dst[4] = make_float4(acc[i][4], acc[i][5], acc[i][6], acc[i][7]);
        }
    }
}

// ---------------------------------------------------------------------------
// Kernel 2: out[n, j] = b[j]  (bias pre-init; scatter then accumulates on top)
// ---------------------------------------------------------------------------
__global__ __launch_bounds__(256) void bias_init_kernel(
    float* __restrict__ out, const float* __restrict__ b)
{
    int idx = blockIdx.x * blockDim.x + threadIdx.x;          // float4 index
    const int total4 = N_NODES * OUT_DIM / 4;
    if (idx < total4) {
        int colgrp = idx & (OUT_DIM / 4 - 1);                 // 0..31
        float4 bv = *(const float4*)&b[colgrp * 4];
        *(float4*)&out[(size_t)idx * 4] = bv;
    }
}

// ---------------------------------------------------------------------------
// Kernel 3: edge scatter. One warp per edge:
//   lane L handles columns 4L..4L+3 -> one 16B gather + one red.global.v4.f32
// ---------------------------------------------------------------------------
__global__ __launch_bounds__(256) void scatter_kernel(
    const int*   __restrict__ edge_src,
    const int*   __restrict__ edge_dst,
    const float* __restrict__ edge_vals,
    float*       __restrict__ out)
{
    const int gw   = (blockIdx.x * blockDim.x + threadIdx.x) >> 5;  // edge id
    const int lane = threadIdx.x & 31;
    if (gw >= N_EDGES) return;

    const int   s = __ldg(&edge_src[gw]);
    const int   d = __ldg(&edge_dst[gw]);
    const float w = __ldg(&edge_vals[gw]);

    const float4 hv = *(const float4*)&g_h[(size_t)s * OUT_DIM + lane * 4];
    float4 m = make_float4(hv.x * w, hv.y * w, hv.z * w, hv.w * w);

    float* p = &out[(size_t)d * OUT_DIM + lane * 4];
    asm volatile("red.global.add.v4.f32 [%0], {%1, %2, %3, %4};"
                 :: "l"(p), "f"(m.x), "f"(m.y), "f"(m.z), "f"(m.w)
                 : "memory");
}

// ---------------------------------------------------------------------------
// Launch
// ---------------------------------------------------------------------------
extern "C" void kernel_launch(void* const* d_in, const int* in_sizes, int n_in,
                              void* d_out, int out_size)
{
    const float* feat  = (const float*)d_in[0];
    const int*   esrc  = (const int*)  d_in[1];
    const int*   edst  = (const int*)  d_in[2];
    const float* evals = (const float*)d_in[3];
    const float* W     = (const float*)d_in[4];
    const float* b     = (const float*)d_in[5];
    float*       out   = (float*)d_out;

    (void)in_sizes; (void)n_in; (void)out_size;

    // h = X @ W
    gemm_kernel<<<(N_NODES + BM - 1) / BM, 256>>>(feat, W);

    // out = broadcast(b)
    const int total4 = N_NODES * OUT_DIM / 4;
    bias_init_kernel<<<(total4 + 255) / 256, 256>>>(out, b);

    // out[dst] += val * h[src]
    const long long scatter_threads = (long long)N_EDGES * 32;
    scatter_kernel<<<(unsigned)((scatter_threads + 255) / 256), 256>>>(
        esrc, edst, evals, out);
}

// round 6
// speedup vs baseline: 1.7620x; 1.7620x over previous
#include <cuda_runtime.h>

#define N_NODES 100000
#define IN_DIM  256
#define OUT_DIM 128
#define N_EDGES 3200000

#define SCAN_BLK 512
#define N_SCAN_BLOCKS ((N_NODES + SCAN_BLK - 1) / SCAN_BLK)   // 196

// ---------------------------------------------------------------------------
// Static scratch (allocation-guard rules: __device__ globals only)
// ---------------------------------------------------------------------------
__device__ float g_h[(size_t)N_NODES * OUT_DIM];      // 51.2 MB: h = X @ W
__device__ int   g_start[N_NODES + 1];                // CSR row starts
__device__ int   g_cursor[N_NODES];                   // fill cursors (hist counts first)
__device__ int   g_bsum[N_SCAN_BLOCKS];               // scan block sums
__device__ int2  g_pairs[N_EDGES];                    // 25.6 MB: (src, val) by dst bucket

// ---------------------------------------------------------------------------
// f32x2 helpers (packed fp32 FMA — sm_10x, PTX-only per SASS_QUICKREF)
// ---------------------------------------------------------------------------
__device__ __forceinline__ unsigned long long pack_f32x2(float x, float y) {
    unsigned long long r;
    asm("mov.b64 %0, {%1, %2};" : "=l"(r) : "f"(x), "f"(y));
    return r;
}
__device__ __forceinline__ unsigned long long fma_f32x2(
    unsigned long long a, unsigned long long b, unsigned long long c) {
    unsigned long long d;
    asm("fma.rn.f32x2 %0, %1, %2, %3;" : "=l"(d) : "l"(a), "l"(b), "l"(c));
    return d;
}
__device__ __forceinline__ void unpack_f32x2(unsigned long long v, float& x, float& y) {
    asm("mov.b64 {%0, %1}, %2;" : "=f"(x), "=f"(y) : "l"(v));
}

// ---------------------------------------------------------------------------
// Kernel 1: SGEMM  h = X[100000,256] @ W[256,128]
// 128x128 tile, BK=16, 256 threads, 8x8 per-thread tile, FFMA2 inner loop.
// ---------------------------------------------------------------------------
#define BM 128
#define BN 128
#define BK 16

__global__ __launch_bounds__(256) void gemm_kernel(
    const float* __restrict__ A,   // [N_NODES, IN_DIM]
    const float* __restrict__ W)   // [IN_DIM, OUT_DIM]
{
    __shared__ float As[BK][BM + 4];
    __shared__ float Bs[BK][BN];

    const int tid       = threadIdx.x;
    const int block_row = blockIdx.x * BM;
    const int ty        = tid >> 4;   // 0..15
    const int tx        = tid & 15;   // 0..15

    // acc2[i][j] holds packed (acc[i][2j], acc[i][2j+1])
    unsigned long long acc2[8][4];
#pragma unroll
    for (int i = 0; i < 8; i++)
#pragma unroll
        for (int j = 0; j < 4; j++) acc2[i][j] = 0ull;

#pragma unroll 1
    for (int kt = 0; kt < IN_DIM / BK; kt++) {
        const int k0 = kt * BK;

        // A tile: 128 rows x 16 cols, transposed into As
#pragma unroll
        for (int half = 0; half < 2; half++) {
            int idx = tid + half * 256;
            int row = idx >> 2;
            int c4  = idx & 3;
            int gr  = block_row + row;
            float4 v = make_float4(0.f, 0.f, 0.f, 0.f);
            if (gr < N_NODES)
                v = *(const float4*)&A[(size_t)gr * IN_DIM + k0 + c4 * 4];
            As[c4 * 4 + 0][row] = v.x;
            As[c4 * 4 + 1][row] = v.y;
            As[c4 * 4 + 2][row] = v.z;
            As[c4 * 4 + 3][row] = v.w;
        }

        // B tile: 16 x 128
#pragma unroll
        for (int half = 0; half < 2; half++) {
            int idx = tid + half * 256;
            int row = idx >> 5;
            int c   = idx & 31;
            *(float4*)&Bs[row][c * 4] =
                *(const float4*)&W[(size_t)(k0 + row) * OUT_DIM + c * 4];
        }

        __syncthreads();

#pragma unroll
        for (int k = 0; k < BK; k++) {
            float a[8];
            *(float4*)&a[0] = *(const float4*)&As[k][ty * 8];
            *(float4*)&a[4] = *(const float4*)&As[k][ty * 8 + 4];
            // b pairs: 8 floats = 4 x 64-bit (32B-aligned in smem)
            unsigned long long b2[4];
            const unsigned long long* bp =
                (const unsigned long long*)&Bs[k][tx * 8];
#pragma unroll
            for (int j = 0; j < 4; j++) b2[j] = bp[j];
#pragma unroll
            for (int i = 0; i < 8; i++) {
                unsigned long long a2 = pack_f32x2(a[i], a[i]);
#pragma unroll
                for (int j = 0; j < 4; j++)
                    acc2[i][j] = fma_f32x2(a2, b2[j], acc2[i][j]);
            }
        }

        __syncthreads();
    }

    // epilogue
#pragma unroll
    for (int i = 0; i < 8; i++) {
        int gr = block_row + ty * 8 + i;
        if (gr < N_NODES) {
            float o[8];
#pragma unroll
            for (int j = 0; j < 4; j++)
                unpack_f32x2(acc2[i][j], o[2 * j], o[2 * j + 1]);
            float* dst = &g_h[(size_t)gr * OUT_DIM + tx * 8];
            *(float4*)&dst[0] = make_float4(o[0], o[1], o[2], o[3]);
            *(float4*)&dst[4] = make_float4(o[4], o[5], o[6], o[7]);
        }
    }
}

// ---------------------------------------------------------------------------
// CSR build: zero -> histogram -> scan(3 kernels) -> reorder
// ---------------------------------------------------------------------------
__global__ __launch_bounds__(256) void zero_count_kernel() {
    int i = blockIdx.x * blockDim.x + threadIdx.x;
    if (i < N_NODES) g_cursor[i] = 0;
}

__global__ __launch_bounds__(256) void hist_kernel(const int* __restrict__ edst) {
    int i = blockIdx.x * blockDim.x + threadIdx.x;
    if (i < N_EDGES) atomicAdd(&g_cursor[edst[i]], 1);
}

// per-block exclusive scan of counts -> g_start (partial); block totals -> g_bsum
__global__ __launch_bounds__(SCAN_BLK) void scan1_kernel() {
    __shared__ int s[SCAN_BLK];
    int tid = threadIdx.x;
    int idx = blockIdx.x * SCAN_BLK + tid;
    int c = (idx < N_NODES) ? g_cursor[idx] : 0;
    s[tid] = c;
    __syncthreads();
#pragma unroll
    for (int off = 1; off < SCAN_BLK; off <<= 1) {
        int t = (tid >= off) ? s[tid - off] : 0;
        __syncthreads();
        s[tid] += t;
        __syncthreads();
    }
    if (idx < N_NODES) g_start[idx] = s[tid] - c;      // exclusive within block
    if (tid == SCAN_BLK - 1) g_bsum[blockIdx.x] = s[tid];
}

// exclusive scan of the 196 block sums (single block)
__global__ __launch_bounds__(256) void scan2_kernel() {
    __shared__ int s[256];
    int tid = threadIdx.x;
    int c = (tid < N_SCAN_BLOCKS) ? g_bsum[tid] : 0;
    s[tid] = c;
    __syncthreads();
#pragma unroll
    for (int off = 1; off < 256; off <<= 1) {
        int t = (tid >= off) ? s[tid - off] : 0;
        __syncthreads();
        s[tid] += t;
        __syncthreads();
    }
    if (tid < N_SCAN_BLOCKS) g_bsum[tid] = s[tid] - c;
}

// add block offsets; init cursors; set sentinel
__global__ __launch_bounds__(SCAN_BLK) void scan3_kernel() {
    int idx = blockIdx.x * SCAN_BLK + threadIdx.x;
    if (idx < N_NODES) {
        int v = g_start[idx] + g_bsum[blockIdx.x];
        g_start[idx]  = v;
        g_cursor[idx] = v;
    }
    if (idx == 0) g_start[N_NODES] = N_EDGES;
}

__global__ __launch_bounds__(256) void reorder_kernel(
    const int*   __restrict__ esrc,
    const int*   __restrict__ edst,
    const float* __restrict__ evals)
{
    int i = blockIdx.x * blockDim.x + threadIdx.x;
    if (i >= N_EDGES) return;
    int d   = edst[i];
    int pos = atomicAdd(&g_cursor[d], 1);
    g_pairs[pos] = make_int2(esrc[i], __float_as_int(evals[i]));
}

// ---------------------------------------------------------------------------
// Gather: one warp per node. lane L owns columns 4L..4L+3.
// out[n] = b + sum_{e in bucket(n)} val_e * h[src_e]   (single write, no atomics)
// ---------------------------------------------------------------------------
__global__ __launch_bounds__(256) void gather_kernel(
    float* __restrict__ out, const float* __restrict__ b)
{
    const int gw   = (blockIdx.x * blockDim.x + threadIdx.x) >> 5;  // node id
    const int lane = threadIdx.x & 31;
    if (gw >= N_NODES) return;

    const int start = __ldg(&g_start[gw]);
    const int end   = __ldg(&g_start[gw + 1]);

    float4 acc = make_float4(0.f, 0.f, 0.f, 0.f);

    int e = start;
    for (; e + 2 <= end; e += 2) {
        const int2 p0 = __ldg(&g_pairs[e]);
        const int2 p1 = __ldg(&g_pairs[e + 1]);
        const float4 h0 = *(const float4*)&g_h[(size_t)p0.x * OUT_DIM + lane * 4];
        const float4 h1 = *(const float4*)&g_h[(size_t)p1.x * OUT_DIM + lane * 4];
        const float v0 = __int_as_float(p0.y);
        const float v1 = __int_as_float(p1.y);
        acc.x = fmaf(v0, h0.x, acc.x);
        acc.y = fmaf(v0, h0.y, acc.y);
        acc.z = fmaf(v0, h0.z, acc.z);
        acc.w = fmaf(v0, h0.w, acc.w);
        acc.x = fmaf(v1, h1.x, acc.x);
        acc.y = fmaf(v1, h1.y, acc.y);
        acc.z = fmaf(v1, h1.z, acc.z);
        acc.w = fmaf(v1, h1.w, acc.w);
    }
    if (e < end) {
        const int2 p = __ldg(&g_pairs[e]);
        const float4 hv = *(const float4*)&g_h[(size_t)p.x * OUT_DIM + lane * 4];
        const float v = __int_as_float(p.y);
        acc.x = fmaf(v, hv.x, acc.x);
        acc.y = fmaf(v, hv.y, acc.y);
        acc.z = fmaf(v, hv.z, acc.z);
        acc.w = fmaf(v, hv.w, acc.w);
    }

    const float4 bv = *(const float4*)&b[lane * 4];
    float4 o = make_float4(acc.x + bv.x, acc.y + bv.y, acc.z + bv.z, acc.w + bv.w);
    *(float4*)&out[(size_t)gw * OUT_DIM + lane * 4] = o;
}

// ---------------------------------------------------------------------------
// Launch
// ---------------------------------------------------------------------------
extern "C" void kernel_launch(void* const* d_in, const int* in_sizes, int n_in,
                              void* d_out, int out_size)
{
    const float* feat  = (const float*)d_in[0];
    const int*   esrc  = (const int*)  d_in[1];
    const int*   edst  = (const int*)  d_in[2];
    const float* evals = (const float*)d_in[3];
    const float* W     = (const float*)d_in[4];
    const float* b     = (const float*)d_in[5];
    float*       out   = (float*)d_out;

    (void)in_sizes; (void)n_in; (void)out_size;

    // dense transform
    gemm_kernel<<<(N_NODES + BM - 1) / BM, 256>>>(feat, W);

    // CSR build (counting sort by dst)
    zero_count_kernel<<<(N_NODES + 255) / 256, 256>>>();
    hist_kernel<<<(N_EDGES + 255) / 256, 256>>>(edst);
    scan1_kernel<<<N_SCAN_BLOCKS, SCAN_BLK>>>();
    scan2_kernel<<<1, 256>>>();
    scan3_kernel<<<N_SCAN_BLOCKS, SCAN_BLK>>>();
    reorder_kernel<<<(N_EDGES + 255) / 256, 256>>>(esrc, edst, evals);

    // per-node gather + fused bias (single coalesced write per output row)
    const long long gthreads = (long long)N_NODES * 32;
    gather_kernel<<<(unsigned)((gthreads + 255) / 256), 256>>>(out, b);
}

// round 8
// speedup vs baseline: 1.9647x; 1.1150x over previous
#include <cuda_runtime.h>
#include <cuda_fp16.h>

#define N_NODES 100000
#define IN_DIM  256
#define OUT_DIM 128
#define N_EDGES 3200000

#define SCAN_BLK 512
#define N_SCAN_BLOCKS ((N_NODES + SCAN_BLK - 1) / SCAN_BLK)   // 196

// ---------------------------------------------------------------------------
// Static scratch (allocation-guard rules: __device__ globals only)
// ---------------------------------------------------------------------------
__device__ __half g_h[(size_t)N_NODES * OUT_DIM];     // 25.6 MB: h = X @ W (fp16)
__device__ int    g_start[N_NODES + 1];               // CSR row starts
__device__ int    g_cursor[N_NODES];                  // fill cursors (hist counts first)
__device__ int    g_bsum[N_SCAN_BLOCKS];              // scan block sums
__device__ int2   g_pairs[N_EDGES];                   // 25.6 MB: (src, val) by dst bucket

// ---------------------------------------------------------------------------
// f32x2 helpers (packed fp32 FMA — sm_10x, PTX-only per SASS_QUICKREF)
// ---------------------------------------------------------------------------
__device__ __forceinline__ unsigned long long pack_f32x2(float x, float y) {
    unsigned long long r;
    asm("mov.b64 %0, {%1, %2};" : "=l"(r) : "f"(x), "f"(y));
    return r;
}
__device__ __forceinline__ unsigned long long fma_f32x2(
    unsigned long long a, unsigned long long b, unsigned long long c) {
    unsigned long long d;
    asm("fma.rn.f32x2 %0, %1, %2, %3;" : "=l"(d) : "l"(a), "l"(b), "l"(c));
    return d;
}
__device__ __forceinline__ void unpack_f32x2(unsigned long long v, float& x, float& y) {
    asm("mov.b64 {%0, %1}, %2;" : "=f"(x), "=f"(y) : "l"(v));
}

// ---------------------------------------------------------------------------
// Kernel 1: SGEMM  h = X[100000,256] @ W[256,128]  -> fp16 h
// 128x128 tile, BK=16, 256 threads, 8x8 per-thread tile, FFMA2 inner loop.
// ---------------------------------------------------------------------------
#define BM 128
#define BN 128
#define BK 16

__global__ __launch_bounds__(256) void gemm_kernel(
    const float* __restrict__ A,   // [N_NODES, IN_DIM]
    const float* __restrict__ W)   // [IN_DIM, OUT_DIM]
{
    __shared__ float As[BK][BM + 4];
    __shared__ float Bs[BK][BN];

    const int tid       = threadIdx.x;
    const int block_row = blockIdx.x * BM;
    const int ty        = tid >> 4;   // 0..15
    const int tx        = tid & 15;   // 0..15

    // acc2[i][j] holds packed (acc[i][2j], acc[i][2j+1])
    unsigned long long acc2[8][4];
#pragma unroll
    for (int i = 0; i < 8; i++)
#pragma unroll
        for (int j = 0; j < 4; j++) acc2[i][j] = 0ull;

#pragma unroll 1
    for (int kt = 0; kt < IN_DIM / BK; kt++) {
        const int k0 = kt * BK;

        // A tile: 128 rows x 16 cols, transposed into As
#pragma unroll
        for (int half = 0; half < 2; half++) {
            int idx = tid + half * 256;
            int row = idx >> 2;
            int c4  = idx & 3;
            int gr  = block_row + row;
            float4 v = make_float4(0.f, 0.f, 0.f, 0.f);
            if (gr < N_NODES)
                v = *(const float4*)&A[(size_t)gr * IN_DIM + k0 + c4 * 4];
            As[c4 * 4 + 0][row] = v.x;
            As[c4 * 4 + 1][row] = v.y;
            As[c4 * 4 + 2][row] = v.z;
            As[c4 * 4 + 3][row] = v.w;
        }

        // B tile: 16 x 128
#pragma unroll
        for (int half = 0; half < 2; half++) {
            int idx = tid + half * 256;
            int row = idx >> 5;
            int c   = idx & 31;
            *(float4*)&Bs[row][c * 4] =
                *(const float4*)&W[(size_t)(k0 + row) * OUT_DIM + c * 4];
        }

        __syncthreads();

#pragma unroll
        for (int k = 0; k < BK; k++) {
            float a[8];
            *(float4*)&a[0] = *(const float4*)&As[k][ty * 8];
            *(float4*)&a[4] = *(const float4*)&As[k][ty * 8 + 4];
            unsigned long long b2[4];
            const unsigned long long* bp =
                (const unsigned long long*)&Bs[k][tx * 8];
#pragma unroll
            for (int j = 0; j < 4; j++) b2[j] = bp[j];
#pragma unroll
            for (int i = 0; i < 8; i++) {
                unsigned long long a2 = pack_f32x2(a[i], a[i]);
#pragma unroll
                for (int j = 0; j < 4; j++)
                    acc2[i][j] = fma_f32x2(a2, b2[j], acc2[i][j]);
            }
        }

        __syncthreads();
    }

    // epilogue: convert to fp16, one 16B store per (thread, row)
#pragma unroll
    for (int i = 0; i < 8; i++) {
        int gr = block_row + ty * 8 + i;
        if (gr < N_NODES) {
            float o[8];
#pragma unroll
            for (int j = 0; j < 4; j++)
                unpack_f32x2(acc2[i][j], o[2 * j], o[2 * j + 1]);
            __half2 hv[4];
#pragma unroll
            for (int j = 0; j < 4; j++)
                hv[j] = __floats2half2_rn(o[2 * j], o[2 * j + 1]);
            *(uint4*)&g_h[(size_t)gr * OUT_DIM + tx * 8] = *(const uint4*)hv;
        }
    }
}

// ---------------------------------------------------------------------------
// CSR build: zero -> histogram -> scan(3 kernels) -> reorder
// ---------------------------------------------------------------------------
__global__ __launch_bounds__(256) void zero_count_kernel() {
    int i = blockIdx.x * blockDim.x + threadIdx.x;
    if (i < N_NODES) g_cursor[i] = 0;
}

__global__ __launch_bounds__(256) void hist_kernel(const int* __restrict__ edst) {
    int i = blockIdx.x * blockDim.x + threadIdx.x;
    if (i < N_EDGES) atomicAdd(&g_cursor[edst[i]], 1);
}

__global__ __launch_bounds__(SCAN_BLK) void scan1_kernel() {
    __shared__ int s[SCAN_BLK];
    int tid = threadIdx.x;
    int idx = blockIdx.x * SCAN_BLK + tid;
    int c = (idx < N_NODES) ? g_cursor[idx] : 0;
    s[tid] = c;
    __syncthreads();
#pragma unroll
    for (int off = 1; off < SCAN_BLK; off <<= 1) {
        int t = (tid >= off) ? s[tid - off] : 0;
        __syncthreads();
        s[tid] += t;
        __syncthreads();
    }
    if (idx < N_NODES) g_start[idx] = s[tid] - c;      // exclusive within block
    if (tid == SCAN_BLK - 1) g_bsum[blockIdx.x] = s[tid];
}

__global__ __launch_bounds__(256) void scan2_kernel() {
    __shared__ int s[256];
    int tid = threadIdx.x;
    int c = (tid < N_SCAN_BLOCKS) ? g_bsum[tid] : 0;
    s[tid] = c;
    __syncthreads();
#pragma unroll
    for (int off = 1; off < 256; off <<= 1) {
        int t = (tid >= off) ? s[tid - off] : 0;
        __syncthreads();
        s[tid] += t;
        __syncthreads();
    }
    if (tid < N_SCAN_BLOCKS) g_bsum[tid] = s[tid] - c;
}

__global__ __launch_bounds__(SCAN_BLK) void scan3_kernel() {
    int idx = blockIdx.x * SCAN_BLK + threadIdx.x;
    if (idx < N_NODES) {
        int v = g_start[idx] + g_bsum[blockIdx.x];
        g_start[idx]  = v;
        g_cursor[idx] = v;
    }
    if (idx == 0) g_start[N_NODES] = N_EDGES;
}

__global__ __launch_bounds__(256) void reorder_kernel(
    const int*   __restrict__ esrc,
    const int*   __restrict__ edst,
    const float* __restrict__ evals)
{
    int i = blockIdx.x * blockDim.x + threadIdx.x;
    if (i >= N_EDGES) return;
    int d   = edst[i];
    int pos = atomicAdd(&g_cursor[d], 1);
    g_pairs[pos] = make_int2(esrc[i], __float_as_int(evals[i]));
}

// ---------------------------------------------------------------------------
// Gather: one warp per node. lane L owns columns 4L..4L+3 (4 halves = 8B).
// out[n] = b + sum_{e in bucket(n)} val_e * h[src_e]   (single write, no atomics)
// ---------------------------------------------------------------------------
__device__ __forceinline__ void acc_edge(
    float4& acc, int2 p, int lane)
{
    const float v = __int_as_float(p.y);
    const uint2 raw = __ldg((const uint2*)&g_h[(size_t)p.x * OUT_DIM + lane * 4]);
    const float2 f01 = __half22float2(*(const __half2*)&raw.x);
    const float2 f23 = __half22float2(*(const __half2*)&raw.y);
    acc.x = fmaf(v, f01.x, acc.x);
    acc.y = fmaf(v, f01.y, acc.y);
    acc.z = fmaf(v, f23.x, acc.z);
    acc.w = fmaf(v, f23.y, acc.w);
}

__global__ __launch_bounds__(256) void gather_kernel(
    float* __restrict__ out, const float* __restrict__ b)
{
    const int gw   = (blockIdx.x * blockDim.x + threadIdx.x) >> 5;  // node id
    const int lane = threadIdx.x & 31;
    if (gw >= N_NODES) return;

    const int start = __ldg(&g_start[gw]);
    const int end   = __ldg(&g_start[gw + 1]);

    float4 acc = make_float4(0.f, 0.f, 0.f, 0.f);

    int e = start;
    // unroll-4 for MLP (avg degree 32)
    for (; e + 4 <= end; e += 4) {
        const int2 p0 = __ldg(&g_pairs[e]);
        const int2 p1 = __ldg(&g_pairs[e + 1]);
        const int2 p2 = __ldg(&g_pairs[e + 2]);
        const int2 p3 = __ldg(&g_pairs[e + 3]);
        acc_edge(acc, p0, lane);
        acc_edge(acc, p1, lane);
        acc_edge(acc, p2, lane);
        acc_edge(acc, p3, lane);
    }
    for (; e < end; e++) {
        const int2 p = __ldg(&g_pairs[e]);
        acc_edge(acc, p, lane);
    }

    const float4 bv = *(const float4*)&b[lane * 4];
    float4 o = make_float4(acc.x + bv.x, acc.y + bv.y, acc.z + bv.z, acc.w + bv.w);
    *(float4*)&out[(size_t)gw * OUT_DIM + lane * 4] = o;
}

// ---------------------------------------------------------------------------
// Launch
// ---------------------------------------------------------------------------
extern "C" void kernel_launch(void* const* d_in, const int* in_sizes, int n_in,
                              void* d_out, int out_size)
{
    const float* feat  = (const float*)d_in[0];
    const int*   esrc  = (const int*)  d_in[1];
    const int*   edst  = (const int*)  d_in[2];
    const float* evals = (const float*)d_in[3];
    const float* W     = (const float*)d_in[4];
    const float* b     = (const float*)d_in[5];
    float*       out   = (float*)d_out;

    (void)in_sizes; (void)n_in; (void)out_size;

    // dense transform (fp16 h)
    gemm_kernel<<<(N_NODES + BM - 1) / BM, 256>>>(feat, W);

    // CSR build (counting sort by dst)
    zero_count_kernel<<<(N_NODES + 255) / 256, 256>>>();
    hist_kernel<<<(N_EDGES + 255) / 256, 256>>>(edst);
    scan1_kernel<<<N_SCAN_BLOCKS, SCAN_BLK>>>();
    scan2_kernel<<<1, 256>>>();
    scan3_kernel<<<N_SCAN_BLOCKS, SCAN_BLK>>>();
    reorder_kernel<<<(N_EDGES + 255) / 256, 256>>>(esrc, edst, evals);

    // per-node gather + fused bias (single coalesced write per output row)
    const long long gthreads = (long long)N_NODES * 32;
    gather_kernel<<<(unsigned)((gthreads + 255) / 256), 256>>>(out, b);
}